// round 1
// baseline (speedup 1.0000x reference)
#include <cuda_runtime.h>

#define NB 8
#define NC 512
#define NL 1024
#define NH 8
#define ND 64
#define GC 64
#define LTILE 128

// Scratch (allocation-free rule: __device__ globals)
__device__ float g_qh[NB*NC*NL];   // conv outputs, [b][h*64+d][l]
__device__ float g_kh[NB*NC*NL];
__device__ float g_vh[NB*NC*NL];
__device__ float g_o [NB*NL*NC];   // attention output, [b][l][c]

// ---------------------------------------------------------------------------
// Grouped Conv1d: k=3, reflect pad, groups=8. grid (8 ltiles, B*H), 256 thr.
// out[b, g*64+c, l] = sum_{i<64,t<3} w[(g*64+c), i, t] * x_refl[b, g*64+i, l-1+t]
// ---------------------------------------------------------------------------
__global__ __launch_bounds__(256, 2)
void conv_kernel(const float* __restrict__ x, const float* __restrict__ w, int which)
{
    float* outb = (which == 0) ? g_qh : (which == 1) ? g_kh : g_vh;
    __shared__ float xs[GC][LTILE+2];

    int bg = blockIdx.y;
    int b  = bg >> 3, g = bg & 7;
    int lt = blockIdx.x * LTILE;
    int tid = threadIdx.x;

    const float* xg = x + (size_t)(b*NC + g*GC) * NL;
    for (int i = tid; i < GC*(LTILE+2); i += 256) {
        int ch = i / (LTILE+2);
        int lo = i - ch*(LTILE+2);
        int lp = lt - 1 + lo;                       // global position
        lp = (lp < 0) ? 1 : ((lp >= NL) ? (2*NL - 2 - lp) : lp);  // reflect
        xs[ch][lo] = xg[ch*NL + lp];
    }
    __syncthreads();

    int c  = tid >> 2;      // out channel within group, 0..63
    int lq = tid & 3;       // l sub-slot
    const float* wc = w + (size_t)(g*GC + c) * 192;

    float acc[4][8];
    #pragma unroll
    for (int rp = 0; rp < 4; ++rp)
        #pragma unroll
        for (int r = 0; r < 8; ++r) acc[rp][r] = 0.f;

    for (int i = 0; i < GC; ++i) {
        float w0 = wc[i*3+0];
        float w1 = wc[i*3+1];
        float w2 = wc[i*3+2];
        #pragma unroll
        for (int rp = 0; rp < 4; ++rp) {
            int l0 = rp*32 + lq*8;
            float xr[10];
            #pragma unroll
            for (int r = 0; r < 10; ++r) xr[r] = xs[i][l0 + r];
            #pragma unroll
            for (int r = 0; r < 8; ++r)
                acc[rp][r] += w0*xr[r] + w1*xr[r+1] + w2*xr[r+2];
        }
    }

    float* og = outb + (size_t)(b*NC + g*GC + c) * NL + lt;
    #pragma unroll
    for (int rp = 0; rp < 4; ++rp) {
        int l0 = rp*32 + lq*8;
        *(float4*)(og + l0)     = make_float4(acc[rp][0], acc[rp][1], acc[rp][2], acc[rp][3]);
        *(float4*)(og + l0 + 4) = make_float4(acc[rp][4], acc[rp][5], acc[rp][6], acc[rp][7]);
    }
}

// ---------------------------------------------------------------------------
// Causal flash attention, fp32. grid (8 qtiles, B*H), 128 threads.
// Thread t owns query row l = qt*128 + t. K/V tiles of 32 keys in smem [m][d].
// scores scaled by 1/sqrt(H); online softmax in registers.
// ---------------------------------------------------------------------------
__global__ __launch_bounds__(128, 2)
void attn_kernel()
{
    __shared__ float Ks[32][68];
    __shared__ float Vs[32][68];

    int bh  = blockIdx.y;
    int qt  = 7 - blockIdx.x;           // heavy tiles launch first
    int tid = threadIdx.x;
    int row = qt*128 + tid;

    const float* Qb = g_qh + (size_t)bh * ND * NL;
    const float* Kb = g_kh + (size_t)bh * ND * NL;
    const float* Vb = g_vh + (size_t)bh * ND * NL;

    float q[ND];
    #pragma unroll
    for (int d = 0; d < ND; ++d) q[d] = Qb[d*NL + row];

    float o[ND];
    #pragma unroll
    for (int d = 0; d < ND; ++d) o[d] = 0.f;
    float mR = -1e30f, sR = 0.f;

    const float scale = 0.35355339059327373f;   // 1/sqrt(8)
    int nkt = 4*qt + 4;

    for (int kt = 0; kt < nkt; ++kt) {
        __syncthreads();
        #pragma unroll
        for (int it = 0; it < 16; ++it) {
            int idx = it*128 + tid;
            int d = idx >> 5, m = idx & 31;
            Ks[m][d] = Kb[d*NL + kt*32 + m];
            Vs[m][d] = Vb[d*NL + kt*32 + m];
        }
        __syncthreads();

        float s[32];
        #pragma unroll
        for (int m = 0; m < 32; ++m) {
            const float4* kr = (const float4*)(&Ks[m][0]);
            float a = 0.f;
            #pragma unroll
            for (int d4 = 0; d4 < 16; ++d4) {
                float4 kv = kr[d4];
                a += q[4*d4+0]*kv.x + q[4*d4+1]*kv.y + q[4*d4+2]*kv.z + q[4*d4+3]*kv.w;
            }
            s[m] = a * scale;
        }

        int mbase = kt*32;
        if (mbase + 31 > row) {
            #pragma unroll
            for (int m = 0; m < 32; ++m)
                if (mbase + m > row) s[m] = -1e30f;
        }

        float tmax = mR;
        #pragma unroll
        for (int m = 0; m < 32; ++m) tmax = fmaxf(tmax, s[m]);
        float corr = __expf(mR - tmax);
        mR = tmax;
        sR *= corr;
        #pragma unroll
        for (int d = 0; d < ND; ++d) o[d] *= corr;

        #pragma unroll
        for (int m = 0; m < 32; ++m) {
            float p = __expf(s[m] - tmax);
            sR += p;
            const float4* vr = (const float4*)(&Vs[m][0]);
            #pragma unroll
            for (int d4 = 0; d4 < 16; ++d4) {
                float4 vv = vr[d4];
                o[4*d4+0] += p*vv.x;
                o[4*d4+1] += p*vv.y;
                o[4*d4+2] += p*vv.z;
                o[4*d4+3] += p*vv.w;
            }
        }
    }

    int b = bh >> 3, h = bh & 7;
    float inv = 1.f / sR;
    float* Ob = g_o + ((size_t)(b*NL + row)) * NC + h*ND;
    #pragma unroll
    for (int d4 = 0; d4 < 16; ++d4) {
        ((float4*)Ob)[d4] = make_float4(o[4*d4+0]*inv, o[4*d4+1]*inv,
                                        o[4*d4+2]*inv, o[4*d4+3]*inv);
    }
}

// ---------------------------------------------------------------------------
// Residual add + LayerNorm over channel dim. grid B*L blocks, 128 threads.
// x[c] = o[b,l,c] + init[b,c,l]; y[b,c,l] = (x-mu)*rstd*gamma[c] + beta[c]
// ---------------------------------------------------------------------------
__global__ __launch_bounds__(128)
void ln_kernel(const float* __restrict__ init, const float* __restrict__ gamma,
               const float* __restrict__ beta, float* __restrict__ y)
{
    int bl = blockIdx.x;
    int b  = bl >> 10, l = bl & 1023;
    int tid = threadIdx.x;

    const float4 ov = ((const float4*)(g_o + (size_t)bl * NC))[tid];
    const float* ib = init + (size_t)b * NC * NL + l;
    float x0 = ov.x + ib[(tid*4+0)*NL];
    float x1 = ov.y + ib[(tid*4+1)*NL];
    float x2 = ov.z + ib[(tid*4+2)*NL];
    float x3 = ov.w + ib[(tid*4+3)*NL];

    float s1 = x0 + x1 + x2 + x3;
    float s2 = x0*x0 + x1*x1 + x2*x2 + x3*x3;
    #pragma unroll
    for (int off = 16; off; off >>= 1) {
        s1 += __shfl_xor_sync(0xffffffffu, s1, off);
        s2 += __shfl_xor_sync(0xffffffffu, s2, off);
    }
    __shared__ float r1[4], r2[4];
    int w = tid >> 5;
    if ((tid & 31) == 0) { r1[w] = s1; r2[w] = s2; }
    __syncthreads();
    float S1 = r1[0] + r1[1] + r1[2] + r1[3];
    float S2 = r2[0] + r2[1] + r2[2] + r2[3];

    float mu   = S1 * (1.f/512.f);
    float var  = S2 * (1.f/512.f) - mu*mu;
    float rstd = rsqrtf(var + 1e-5f);

    float4 gv = ((const float4*)gamma)[tid];
    float4 bv = ((const float4*)beta)[tid];
    float* yb = y + (size_t)b * NC * NL + l;
    yb[(tid*4+0)*NL] = (x0 - mu)*rstd*gv.x + bv.x;
    yb[(tid*4+1)*NL] = (x1 - mu)*rstd*gv.y + bv.y;
    yb[(tid*4+2)*NL] = (x2 - mu)*rstd*gv.z + bv.z;
    yb[(tid*4+3)*NL] = (x3 - mu)*rstd*gv.w + bv.w;
}

// ---------------------------------------------------------------------------
extern "C" void kernel_launch(void* const* d_in, const int* in_sizes, int n_in,
                              void* d_out, int out_size)
{
    const float* q     = (const float*)d_in[0];
    const float* k     = (const float*)d_in[1];
    // d_in[2] = mask (causal triu) — implemented analytically, unused
    const float* wq    = (const float*)d_in[3];
    const float* wk    = (const float*)d_in[4];
    const float* wv    = (const float*)d_in[5];
    const float* gamma = (const float*)d_in[6];
    const float* beta  = (const float*)d_in[7];
    float* out = (float*)d_out;

    dim3 cgrid(NL / LTILE, NB * NH);
    conv_kernel<<<cgrid, 256>>>(q, wq, 0);
    conv_kernel<<<cgrid, 256>>>(k, wk, 1);
    conv_kernel<<<cgrid, 256>>>(k, wv, 2);   // v = k

    attn_kernel<<<dim3(8, NB*NH), 128>>>();

    ln_kernel<<<NB*NL, 128>>>(q, gamma, beta, out);
}

// round 2
// speedup vs baseline: 1.1755x; 1.1755x over previous
#include <cuda_runtime.h>

#define NB 8
#define NC 512
#define NL 1024
#define NH 8
#define ND 64
#define GC 64
#define LTILE 128

typedef unsigned long long u64;

// Scratch (allocation-free rule: __device__ globals)
__device__ float g_qh[NB*NC*NL];   // conv outputs, [b][h*64+d][l]
__device__ float g_kh[NB*NC*NL];
__device__ float g_vh[NB*NC*NL];
__device__ float g_o [NB*NL*NC];   // attention output, [b][l][c]

// ---- packed f32x2 helpers (sm_103a) --------------------------------------
__device__ __forceinline__ u64 pk2(float lo, float hi) {
    u64 r; asm("mov.b64 %0, {%1, %2};" : "=l"(r) : "f"(lo), "f"(hi)); return r;
}
__device__ __forceinline__ void upk2(float& lo, float& hi, u64 v) {
    asm("mov.b64 {%0, %1}, %2;" : "=f"(lo), "=f"(hi) : "l"(v));
}
__device__ __forceinline__ u64 fma2(u64 a, u64 b, u64 c) {
    u64 d; asm("fma.rn.f32x2 %0, %1, %2, %3;" : "=l"(d) : "l"(a), "l"(b), "l"(c)); return d;
}
__device__ __forceinline__ u64 mul2(u64 a, u64 b) {
    u64 d; asm("mul.rn.f32x2 %0, %1, %2;" : "=l"(d) : "l"(a), "l"(b)); return d;
}

// ---------------------------------------------------------------------------
// Grouped Conv1d: k=3, reflect pad, groups=8. grid (8 ltiles, B*H), 256 thr.
// ---------------------------------------------------------------------------
__global__ __launch_bounds__(256, 2)
void conv_kernel(const float* __restrict__ x, const float* __restrict__ w, int which)
{
    float* outb = (which == 0) ? g_qh : (which == 1) ? g_kh : g_vh;
    __shared__ float xs[GC][LTILE+2];

    int bg = blockIdx.y;
    int b  = bg >> 3, g = bg & 7;
    int lt = blockIdx.x * LTILE;
    int tid = threadIdx.x;

    const float* xg = x + (size_t)(b*NC + g*GC) * NL;
    for (int i = tid; i < GC*(LTILE+2); i += 256) {
        int ch = i / (LTILE+2);
        int lo = i - ch*(LTILE+2);
        int lp = lt - 1 + lo;
        lp = (lp < 0) ? 1 : ((lp >= NL) ? (2*NL - 2 - lp) : lp);  // reflect
        xs[ch][lo] = xg[ch*NL + lp];
    }
    __syncthreads();

    int c  = tid >> 2;
    int lq = tid & 3;
    const float* wc = w + (size_t)(g*GC + c) * 192;

    float acc[4][8];
    #pragma unroll
    for (int rp = 0; rp < 4; ++rp)
        #pragma unroll
        for (int r = 0; r < 8; ++r) acc[rp][r] = 0.f;

    for (int i = 0; i < GC; ++i) {
        float w0 = wc[i*3+0];
        float w1 = wc[i*3+1];
        float w2 = wc[i*3+2];
        #pragma unroll
        for (int rp = 0; rp < 4; ++rp) {
            int l0 = rp*32 + lq*8;
            float xr[10];
            #pragma unroll
            for (int r = 0; r < 10; ++r) xr[r] = xs[i][l0 + r];
            #pragma unroll
            for (int r = 0; r < 8; ++r)
                acc[rp][r] += w0*xr[r] + w1*xr[r+1] + w2*xr[r+2];
        }
    }

    float* og = outb + (size_t)(b*NC + g*GC + c) * NL + lt;
    #pragma unroll
    for (int rp = 0; rp < 4; ++rp) {
        int l0 = rp*32 + lq*8;
        *(float4*)(og + l0)     = make_float4(acc[rp][0], acc[rp][1], acc[rp][2], acc[rp][3]);
        *(float4*)(og + l0 + 4) = make_float4(acc[rp][4], acc[rp][5], acc[rp][6], acc[rp][7]);
    }
}

// ---------------------------------------------------------------------------
// Causal flash attention, fp32 with packed f32x2 FMAs (2 MAC/issue).
// grid (8 qtiles, B*H), 128 threads. Thread t owns query row qt*128 + t.
// ---------------------------------------------------------------------------
__global__ __launch_bounds__(128, 2)
void attn_kernel()
{
    __shared__ float Ks[32][68];
    __shared__ float Vs[32][68];

    int bh  = blockIdx.y;
    int qt  = 7 - blockIdx.x;           // heavy tiles first
    int tid = threadIdx.x;
    int row = qt*128 + tid;

    const float* Qb = g_qh + (size_t)bh * ND * NL;
    const float* Kb = g_kh + (size_t)bh * ND * NL;
    const float* Vb = g_vh + (size_t)bh * ND * NL;

    // q packed over d pairs
    u64 q2[32];
    #pragma unroll
    for (int d2 = 0; d2 < 32; ++d2)
        q2[d2] = pk2(Qb[(2*d2)*NL + row], Qb[(2*d2+1)*NL + row]);

    u64 o2[32];
    #pragma unroll
    for (int d2 = 0; d2 < 32; ++d2) o2[d2] = 0ull;   // (0.f, 0.f)
    float mR = -1e30f, sR = 0.f;

    const float scale = 0.35355339059327373f;   // 1/sqrt(8)
    int nkt = 4*qt + 4;

    for (int kt = 0; kt < nkt; ++kt) {
        __syncthreads();
        #pragma unroll
        for (int it = 0; it < 16; ++it) {
            int idx = it*128 + tid;
            int d = idx >> 5, m = idx & 31;
            Ks[m][d] = Kb[d*NL + kt*32 + m];
            Vs[m][d] = Vb[d*NL + kt*32 + m];
        }
        __syncthreads();

        float s[32];
        #pragma unroll
        for (int m = 0; m < 32; ++m) {
            const u64* kr = (const u64*)(&Ks[m][0]);
            u64 a2 = 0ull;
            #pragma unroll
            for (int d2 = 0; d2 < 32; ++d2)
                a2 = fma2(q2[d2], kr[d2], a2);
            float alo, ahi; upk2(alo, ahi, a2);
            s[m] = (alo + ahi) * scale;
        }

        int mbase = kt*32;
        if (mbase + 31 > row) {
            #pragma unroll
            for (int m = 0; m < 32; ++m)
                if (mbase + m > row) s[m] = -1e30f;
        }

        float tmax = mR;
        #pragma unroll
        for (int m = 0; m < 32; ++m) tmax = fmaxf(tmax, s[m]);
        float corr = __expf(mR - tmax);
        mR = tmax;
        sR *= corr;
        u64 c2 = pk2(corr, corr);
        #pragma unroll
        for (int d2 = 0; d2 < 32; ++d2) o2[d2] = mul2(o2[d2], c2);

        #pragma unroll
        for (int m = 0; m < 32; ++m) {
            float p = __expf(s[m] - tmax);
            sR += p;
            u64 pp = pk2(p, p);
            const u64* vr = (const u64*)(&Vs[m][0]);
            #pragma unroll
            for (int d2 = 0; d2 < 32; ++d2)
                o2[d2] = fma2(pp, vr[d2], o2[d2]);
        }
    }

    int b = bh >> 3, h = bh & 7;
    float inv = 1.f / sR;
    float* Ob = g_o + ((size_t)(b*NL + row)) * NC + h*ND;
    #pragma unroll
    for (int d4 = 0; d4 < 16; ++d4) {
        float a, bb, c, d;
        upk2(a, bb, o2[2*d4]);
        upk2(c, d,  o2[2*d4+1]);
        ((float4*)Ob)[d4] = make_float4(a*inv, bb*inv, c*inv, d*inv);
    }
}

// ---------------------------------------------------------------------------
// Residual add + LayerNorm over channel, transposed-tile version.
// Block handles 16 consecutive l for one b; all gmem traffic coalesced.
// grid = B * (L/16), 128 threads.
// ---------------------------------------------------------------------------
#define TL 16
__global__ __launch_bounds__(128)
void ln_kernel(const float* __restrict__ init, const float* __restrict__ gamma,
               const float* __restrict__ beta, float* __restrict__ y)
{
    __shared__ float xt[TL][NC + 4];

    int blk = blockIdx.x;
    int b   = blk >> 6;            // L/16 = 64 tiles per batch
    int lt  = (blk & 63) * TL;
    int tid = threadIdx.x;

    const float* ib = init + (size_t)b * NC * NL + lt;
    float*       yb = y    + (size_t)b * NC * NL + lt;

    // Step 1: stage init tile [c][16 l] -> xt[l][c], coalesced gmem reads
    for (int i = tid; i < NC * (TL/4); i += 128) {
        int c = i >> 2, j = i & 3;
        float4 v = *(const float4*)(ib + (size_t)c * NL + 4*j);
        xt[4*j+0][c] = v.x;
        xt[4*j+1][c] = v.y;
        xt[4*j+2][c] = v.z;
        xt[4*j+3][c] = v.w;
    }
    __syncthreads();

    // Step 2: per-row LN. 4 warps, each warp does 4 rows.
    int w = tid >> 5, lane = tid & 31;
    const float* ob_base = g_o + ((size_t)(b*NL + lt)) * NC;
    for (int r = w; r < TL; r += 4) {
        const float4* orow = (const float4*)(ob_base + (size_t)r * NC);
        float4 xv[4];
        float s1 = 0.f, s2 = 0.f;
        #pragma unroll
        for (int kk = 0; kk < 4; ++kk) {
            int c4 = lane + 32*kk;            // float4 index
            float4 ov = orow[c4];
            float4 iv = *(const float4*)(&xt[r][4*c4]);
            xv[kk] = make_float4(ov.x+iv.x, ov.y+iv.y, ov.z+iv.z, ov.w+iv.w);
            s1 += xv[kk].x + xv[kk].y + xv[kk].z + xv[kk].w;
            s2 += xv[kk].x*xv[kk].x + xv[kk].y*xv[kk].y
                + xv[kk].z*xv[kk].z + xv[kk].w*xv[kk].w;
        }
        #pragma unroll
        for (int off = 16; off; off >>= 1) {
            s1 += __shfl_xor_sync(0xffffffffu, s1, off);
            s2 += __shfl_xor_sync(0xffffffffu, s2, off);
        }
        float mu   = s1 * (1.f/512.f);
        float var  = s2 * (1.f/512.f) - mu*mu;
        float rstd = rsqrtf(var + 1e-5f);

        #pragma unroll
        for (int kk = 0; kk < 4; ++kk) {
            int c4 = lane + 32*kk;
            float4 gv = ((const float4*)gamma)[c4];
            float4 bv = ((const float4*)beta)[c4];
            float4 r4;
            r4.x = (xv[kk].x - mu)*rstd*gv.x + bv.x;
            r4.y = (xv[kk].y - mu)*rstd*gv.y + bv.y;
            r4.z = (xv[kk].z - mu)*rstd*gv.z + bv.z;
            r4.w = (xv[kk].w - mu)*rstd*gv.w + bv.w;
            *(float4*)(&xt[r][4*c4]) = r4;
        }
    }
    __syncthreads();

    // Step 3: write y coalesced: y[b, c, lt+4j .. +3] from xt
    for (int i = tid; i < NC * (TL/4); i += 128) {
        int c = i >> 2, j = i & 3;
        float4 v = make_float4(xt[4*j+0][c], xt[4*j+1][c],
                               xt[4*j+2][c], xt[4*j+3][c]);
        *(float4*)(yb + (size_t)c * NL + 4*j) = v;
    }
}

// ---------------------------------------------------------------------------
extern "C" void kernel_launch(void* const* d_in, const int* in_sizes, int n_in,
                              void* d_out, int out_size)
{
    const float* q     = (const float*)d_in[0];
    const float* k     = (const float*)d_in[1];
    // d_in[2] = mask — causal, handled analytically
    const float* wq    = (const float*)d_in[3];
    const float* wk    = (const float*)d_in[4];
    const float* wv    = (const float*)d_in[5];
    const float* gamma = (const float*)d_in[6];
    const float* beta  = (const float*)d_in[7];
    float* out = (float*)d_out;

    dim3 cgrid(NL / LTILE, NB * NH);
    conv_kernel<<<cgrid, 256>>>(q, wq, 0);
    conv_kernel<<<cgrid, 256>>>(k, wk, 1);
    conv_kernel<<<cgrid, 256>>>(k, wv, 2);   // v = k

    attn_kernel<<<dim3(8, NB*NH), 128>>>();

    ln_kernel<<<NB * (NL/TL), 128>>>(q, gamma, beta, out);
}